// round 2
// baseline (speedup 1.0000x reference)
#include <cuda_runtime.h>
#include <cuda_bf16.h>

#define B     4
#define NB    131072
#define K     32
#define NTOT  (B*NB)
#define HALFS 384.0f
#define INVHALF (1.0f/384.0f)

#define THREADS 256
#define GP      2
#define PPB     (THREADS*GP)        // 512 points per block
#define NBLK    (NTOT/PPB)          // 1024 blocks
#define BPB_SHIFT 8                 // 256 blocks per batch

// ---- persistent device scratch (no allocations allowed) ----
#define A_SUM   0      // 512 floats: [(b*K+k)*4 + c]  c=0..2 ce sums, c=3 sigma sum
#define A_CNT   512    // 128 counts
#define A_MSUM  640    // mask-loss scalar
#define A_SSUM  641    // smooth+seed (w-weighted) scalar
#define A_ACC   642    // accuracy count
#define A_TOTAL 643

__device__ float    g_accum[A_TOTAL];   // zero-init at load; re-zeroed by pass3 finalize
__device__ float4   g_ck [B*K];         // cx, cy, cz, thr(=87*2sig^2)
__device__ float4   g_aux[B*K];         // 1/(2sig^2), sigma, 1/cnt, 0
__device__ unsigned g_ctr1, g_ctr2;

// ---------------- pass 1: per-(batch,cluster) sums + finalize centers ----------------
__global__ void __launch_bounds__(THREADS) k_pass1(const float4* __restrict__ emb,
                                                   const float*  __restrict__ lab) {
    __shared__ float4 stg4[THREADS];
    __shared__ int    stgi[THREADS];
    __shared__ float  sbin[K * 5];
    __shared__ bool   lastb;

    int tid  = threadIdx.x;
    int lane = tid & 31;
    int wb   = tid & ~31;
    int b    = blockIdx.x >> BPB_SHIFT;

    if (tid < K * 5) sbin[tid] = 0.f;
    __syncthreads();

    float a0 = 0.f, a1 = 0.f, a2 = 0.f, a3 = 0.f, ac = 0.f;
    int base = blockIdx.x * PPB + tid;

    #pragma unroll 1
    for (int g = 0; g < GP; g++) {
        int n = base + g * THREADS;
        float4 e = emb[n];
        const float* L = lab + (size_t)n * 6;
        float c0 = e.x + (L[1] - HALFS) * INVHALF;
        float c1 = e.y + (L[2] - HALFS) * INVHALF;
        float c2 = e.z + (L[3] - HALFS) * INVHALF;
        int inst = (int)L[5];
        inst = max(0, min(K - 1, inst));

        stg4[tid] = make_float4(c0, c1, c2, e.w);
        stgi[tid] = inst;
        __syncwarp();
        // lane k owns cluster k: scan this warp's 32 staged points
        #pragma unroll
        for (int i = 0; i < 32; i++) {
            float4 v = stg4[wb + i];   // broadcast LDS.128
            int   ii = stgi[wb + i];   // broadcast LDS.32
            if (ii == lane) { a0 += v.x; a1 += v.y; a2 += v.z; a3 += v.w; ac += 1.f; }
        }
        __syncwarp();
    }

    // per-warp partials -> block bins (lane-distinct addresses, tiny)
    atomicAdd(&sbin[lane * 5 + 0], a0);
    atomicAdd(&sbin[lane * 5 + 1], a1);
    atomicAdd(&sbin[lane * 5 + 2], a2);
    atomicAdd(&sbin[lane * 5 + 3], a3);
    atomicAdd(&sbin[lane * 5 + 4], ac);
    __syncthreads();

    // block bins -> global
    if (tid < K * 5) {
        int k = tid / 5, c = tid - k * 5;
        float v = sbin[tid];
        if (c < 4) atomicAdd(&g_accum[A_SUM + ((b << 5) + k) * 4 + c], v);
        else       atomicAdd(&g_accum[A_CNT + (b << 5) + k], v);
    }
    __threadfence();
    __syncthreads();
    if (tid == 0) lastb = (atomicAdd(&g_ctr1, 1u) == (unsigned)(NBLK - 1));
    __syncthreads();

    if (lastb) {   // finalize: centers / sigmas / weights (former pass2)
        if (tid < B * K) {
            float cnt = fmaxf(g_accum[A_CNT + tid], 1.f);
            float inv = 1.f / cnt;
            float cx = g_accum[A_SUM + tid * 4 + 0] * inv;
            float cy = g_accum[A_SUM + tid * 4 + 1] * inv;
            float cz = g_accum[A_SUM + tid * 4 + 2] * inv;
            float sg = g_accum[A_SUM + tid * 4 + 3] * inv;
            float s2 = 2.f * sg * sg;
            g_ck [tid] = make_float4(cx, cy, cz, 87.f * s2);
            g_aux[tid] = make_float4(1.f / s2, sg, inv, 0.f);
        }
        if (tid == 0) g_ctr1 = 0u;
    }
}

// ---------------- pass 3: main N x K loop + finalize (inter loss + combine) ----------------
__global__ void __launch_bounds__(THREADS) k_pass3(const float4* __restrict__ emb,
                                                   const float*  __restrict__ seedp,
                                                   const float*  __restrict__ lab,
                                                   float* __restrict__ out, int out_size) {
    __shared__ float4 sck[K];     // cx,cy,cz,thr
    __shared__ float4 sax[K];     // inv2s2, sigma, 1/cnt, 0
    __shared__ float  rm[8], rs[8], ra[8];
    __shared__ bool   lastb;

    int tid  = threadIdx.x;
    int lane = tid & 31;
    int wid  = tid >> 5;
    int b    = blockIdx.x >> BPB_SHIFT;

    if (tid < K) { sck[tid] = g_ck[(b << 5) + tid]; sax[tid] = g_aux[(b << 5) + tid]; }
    __syncthreads();

    float m = 0.f, ss = 0.f, aloc = 0.f;
    int base = blockIdx.x * PPB + tid;

    #pragma unroll 1
    for (int g = 0; g < GP; g++) {
        int n = base + g * THREADS;
        float4 e = emb[n];
        const float* L = lab + (size_t)n * 6;
        float ce0 = e.x + (L[1] - HALFS) * INVHALF;
        float ce1 = e.y + (L[2] - HALFS) * INVHALF;
        float ce2 = e.z + (L[3] - HALFS) * INVHALF;
        int inst = (int)L[5];
        inst = max(0, min(K - 1, inst));
        float seed = seedp[n];

        unsigned key = 0xFFFFFFFFu;
        unsigned msk = 0u;
        #pragma unroll
        for (int k = 0; k < K; k++) {
            float4 c = sck[k];
            float d0 = ce0 - c.x, d1 = ce1 - c.y, d2 = ce2 - c.z;
            float dist2 = fmaf(d0, d0, fmaf(d1, d1, d2 * d2));
            unsigned cand = (__float_as_uint(dist2) & 0xFFFFFFE0u) | (unsigned)k;
            key = min(key, cand);                 // argmin, ties -> lower k
            if (dist2 < c.w) msk |= (1u << k);    // arg < 87 -> log term matters
        }

        // own-cluster (onehot) terms
        float4 ci = sck[inst];
        float4 ax = sax[inst];
        float d0 = ce0 - ci.x, d1 = ce1 - ci.y, d2 = ce2 - ci.z;
        float di = fmaf(d0, d0, fmaf(d1, d1, d2 * d2));
        float argi = fminf(fmaxf(di * ax.x, 1e-7f), 100.f);
        m += argi;
        float pi = __expf(-argi);
        float ds = seed - pi;
        ss += ax.z * (fabsf(e.w - ax.y) + ds * ds);   // w * (smooth + seed terms)
        aloc += ((key & 31u) == (unsigned)inst) ? 1.f : 0.f;

        // rare log terms (non-inst, arg < 87)
        msk &= ~(1u << inst);
        while (msk) {
            int k = __ffs(msk) - 1; msk &= msk - 1u;
            float4 c  = sck[k];
            float4 a2 = sax[k];
            float e0 = ce0 - c.x, e1 = ce1 - c.y, e2 = ce2 - c.z;
            float dd = fmaf(e0, e0, fmaf(e1, e1, e2 * e2));
            float arg = fminf(fmaxf(dd * a2.x, 1e-7f), 100.f);
            float omp;
            if (arg < 0.0625f) omp = arg * (1.f + arg * (-0.5f + arg * (1.f / 6.f)));
            else               omp = 1.f - __expf(-arg);
            m -= __logf(omp);    // -log1p(-p)
        }
    }

    // block reduction of 3 scalars
    #pragma unroll
    for (int o = 16; o; o >>= 1) {
        m    += __shfl_down_sync(0xFFFFFFFFu, m, o);
        ss   += __shfl_down_sync(0xFFFFFFFFu, ss, o);
        aloc += __shfl_down_sync(0xFFFFFFFFu, aloc, o);
    }
    if (lane == 0) { rm[wid] = m; rs[wid] = ss; ra[wid] = aloc; }
    __syncthreads();
    if (tid == 0) {
        float tm = 0.f, ts = 0.f, ta = 0.f;
        #pragma unroll
        for (int i = 0; i < 8; i++) { tm += rm[i]; ts += rs[i]; ta += ra[i]; }
        atomicAdd(&g_accum[A_MSUM], tm);
        atomicAdd(&g_accum[A_SSUM], ts);
        atomicAdd(&g_accum[A_ACC],  ta);
        __threadfence();
        lastb = (atomicAdd(&g_ctr2, 1u) == (unsigned)(NBLK - 1));
    }
    __syncthreads();

    if (lastb) {   // finalize: inter-cluster hinge + combine + re-zero scratch
        float hs = 0.f;
        if (tid < B * K) {
            int bb = tid >> 5, kk = tid & 31;
            float4 ck = g_ck[tid];
            #pragma unroll
            for (int j = 0; j < K; j++) {
                if (j == kk) continue;
                float4 cj = g_ck[(bb << 5) | j];
                float f0 = ck.x - cj.x, f1 = ck.y - cj.y, f2 = ck.z - cj.z;
                float cd2 = fmaf(f0, f0, fmaf(f1, f1, f2 * f2));
                float d = sqrtf(cd2);
                float h = fmaxf(0.f, 1.f - d);
                hs += h * h;
            }
        }
        #pragma unroll
        for (int o = 16; o; o >>= 1) hs += __shfl_down_sync(0xFFFFFFFFu, hs, o);
        if (lane == 0) rm[wid] = hs;
        __syncthreads();
        if (tid == 0) {
            float htot = 0.f;
            #pragma unroll
            for (int i = 0; i < 8; i++) htot += rm[i];
            float msum = g_accum[A_MSUM];
            float ssum = g_accum[A_SSUM];
            float asum = g_accum[A_ACC];
            float loss = msum * (1.f / ((float)B * (float)NB * (float)K))
                       + ssum * (1.f / ((float)B * (float)K))
                       + htot * (1.f / (2.f * (float)K * (float)(K - 1) * (float)B));
            out[0] = loss;
            if (out_size > 1) out[1] = asum * (1.f / (float)NTOT);
        }
        __syncthreads();   // all reads of g_accum done before re-zero
        for (int i = tid; i < A_TOTAL; i += THREADS) g_accum[i] = 0.f;
        if (tid == 0) g_ctr2 = 0u;
    }
}

extern "C" void kernel_launch(void* const* d_in, const int* in_sizes, int n_in,
                              void* d_out, int out_size) {
    const float4* emb  = (const float4*)d_in[0];
    const float*  seed = (const float*)d_in[1];
    const float*  lab  = (const float*)d_in[2];
    float* out = (float*)d_out;

    k_pass1<<<NBLK, THREADS>>>(emb, lab);
    k_pass3<<<NBLK, THREADS>>>(emb, seed, lab, out, out_size);
}

// round 6
// speedup vs baseline: 1.4029x; 1.4029x over previous
#include <cuda_runtime.h>
#include <cuda_bf16.h>

#define B     4
#define NB    131072
#define K     32
#define NTOT  (B*NB)
#define HALFS 384.0f
#define INVHALF (1.0f/384.0f)

#define THREADS 256
#define GP      2
#define PPB     (THREADS*GP)        // 512 points per block
#define NBLK    (NTOT/PPB)          // 1024 blocks
#define BPB_SHIFT 8                 // 256 blocks per batch

// ---- persistent device scratch (no allocations allowed) ----
#define A_SUM   0      // 512 floats: [(b*K+k)*4 + c]  c=0..2 ce sums, c=3 sigma sum
#define A_CNT   512    // 128 counts
#define A_MSUM  640    // mask-loss scalar
#define A_SSUM  641    // smooth+seed (w-weighted) scalar
#define A_ACC   642    // accuracy count
#define A_TOTAL 643

__device__ float    g_accum[A_TOTAL];   // zero-init at load; re-zeroed by pass3 finalize
__device__ float4   g_ck [B*K];         // cx, cy, cz, thr(=87*2sig^2)
__device__ float4   g_aux[B*K];         // 1/(2sig^2), sigma, 1/cnt, 0
__device__ unsigned g_ctr1, g_ctr2;

// ---------------- pass 1: per-(batch,cluster) sums + finalize centers ----------------
__global__ void __launch_bounds__(THREADS) k_pass1(const float4* __restrict__ emb,
                                                   const float*  __restrict__ lab) {
    __shared__ float4 stg4[THREADS];
    __shared__ int    stgi[THREADS];
    __shared__ float  sbin[K * 5];
    __shared__ bool   lastb;

    int tid  = threadIdx.x;
    int lane = tid & 31;
    int wb   = tid & ~31;
    int b    = blockIdx.x >> BPB_SHIFT;

    if (tid < K * 5) sbin[tid] = 0.f;
    __syncthreads();

    float a0 = 0.f, a1 = 0.f, a2 = 0.f, a3 = 0.f, ac = 0.f;
    int base = blockIdx.x * PPB + tid;

    #pragma unroll 1
    for (int g = 0; g < GP; g++) {
        int n = base + g * THREADS;
        float4 e = emb[n];
        const float* L = lab + (size_t)n * 6;
        float c0 = e.x + (L[1] - HALFS) * INVHALF;
        float c1 = e.y + (L[2] - HALFS) * INVHALF;
        float c2 = e.z + (L[3] - HALFS) * INVHALF;
        int inst = (int)L[5];
        inst = max(0, min(K - 1, inst));

        stg4[tid] = make_float4(c0, c1, c2, e.w);
        stgi[tid] = inst;
        __syncwarp();
        // lane k owns cluster k: scan this warp's 32 staged points
        #pragma unroll
        for (int i = 0; i < 32; i++) {
            float4 v = stg4[wb + i];   // broadcast LDS.128
            int   ii = stgi[wb + i];   // broadcast LDS.32
            if (ii == lane) { a0 += v.x; a1 += v.y; a2 += v.z; a3 += v.w; ac += 1.f; }
        }
        __syncwarp();
    }

    // per-warp partials -> block bins (lane-distinct addresses, tiny)
    atomicAdd(&sbin[lane * 5 + 0], a0);
    atomicAdd(&sbin[lane * 5 + 1], a1);
    atomicAdd(&sbin[lane * 5 + 2], a2);
    atomicAdd(&sbin[lane * 5 + 3], a3);
    atomicAdd(&sbin[lane * 5 + 4], ac);
    __syncthreads();

    // block bins -> global
    if (tid < K * 5) {
        int k = tid / 5, c = tid - k * 5;
        float v = sbin[tid];
        if (c < 4) atomicAdd(&g_accum[A_SUM + ((b << 5) + k) * 4 + c], v);
        else       atomicAdd(&g_accum[A_CNT + (b << 5) + k], v);
    }
    __threadfence();
    __syncthreads();
    if (tid == 0) lastb = (atomicAdd(&g_ctr1, 1u) == (unsigned)(NBLK - 1));
    __syncthreads();

    if (lastb) {   // finalize: centers / sigmas / weights
        if (tid < B * K) {
            float cnt = fmaxf(g_accum[A_CNT + tid], 1.f);
            float inv = 1.f / cnt;
            float cx = g_accum[A_SUM + tid * 4 + 0] * inv;
            float cy = g_accum[A_SUM + tid * 4 + 1] * inv;
            float cz = g_accum[A_SUM + tid * 4 + 2] * inv;
            float sg = g_accum[A_SUM + tid * 4 + 3] * inv;
            float s2 = 2.f * sg * sg;
            g_ck [tid] = make_float4(cx, cy, cz, 87.f * s2);
            g_aux[tid] = make_float4(1.f / s2, sg, inv, 0.f);
        }
        if (tid == 0) g_ctr1 = 0u;
    }
}

// ---------------- pass 3: main N x K loop + finalize (inter loss + combine) ----------------
__global__ void __launch_bounds__(THREADS, 4) k_pass3(const float4* __restrict__ emb,
                                                      const float*  __restrict__ seedp,
                                                      const float*  __restrict__ lab,
                                                      float* __restrict__ out, int out_size) {
    __shared__ float4 sck[K];     // cx,cy,cz,thr
    __shared__ float4 sax[K];     // inv2s2, sigma, 1/cnt, 0
    __shared__ float  rm[8], rs[8], ra[8];
    __shared__ bool   lastb;

    int tid  = threadIdx.x;
    int lane = tid & 31;
    int wid  = tid >> 5;
    int b    = blockIdx.x >> BPB_SHIFT;

    if (tid < K) { sck[tid] = g_ck[(b << 5) + tid]; sax[tid] = g_aux[(b << 5) + tid]; }
    __syncthreads();

    float m = 0.f, ss = 0.f, aloc = 0.f;
    int base = blockIdx.x * PPB + tid;

    #pragma unroll 1
    for (int g = 0; g < GP; g++) {
        int n = base + g * THREADS;
        float4 e = emb[n];
        const float* L = lab + (size_t)n * 6;
        float ce0 = e.x + (L[1] - HALFS) * INVHALF;
        float ce1 = e.y + (L[2] - HALFS) * INVHALF;
        float ce2 = e.z + (L[3] - HALFS) * INVHALF;
        int inst = (int)L[5];
        inst = max(0, min(K - 1, inst));
        float seed = seedp[n];

        float    best = 3.4e38f;
        int      bi   = 0;
        unsigned msk  = 0u;
        #pragma unroll 8
        for (int k = 0; k < K; k++) {
            float4 c = sck[k];
            float d0 = ce0 - c.x, d1 = ce1 - c.y, d2 = ce2 - c.z;
            float dist2 = fmaf(d0, d0, fmaf(d1, d1, d2 * d2));
            bool better = dist2 < best;
            best = better ? dist2 : best;     // FSEL
            bi   = better ? k : bi;           // SEL
            msk |= (dist2 < c.w) ? (1u << k) : 0u;
        }

        // own-cluster (onehot) terms
        float4 ci = sck[inst];
        float4 ax = sax[inst];
        float d0 = ce0 - ci.x, d1 = ce1 - ci.y, d2 = ce2 - ci.z;
        float di = fmaf(d0, d0, fmaf(d1, d1, d2 * d2));
        float argi = fminf(fmaxf(di * ax.x, 1e-7f), 100.f);
        m += argi;
        float pi = __expf(-argi);
        float ds = seed - pi;
        ss += ax.z * (fabsf(e.w - ax.y) + ds * ds);   // w * (smooth + seed terms)
        aloc += (bi == inst) ? 1.f : 0.f;

        // rare log terms (non-inst, arg < 87)
        msk &= ~(1u << inst);
        while (msk) {
            int k = __ffs(msk) - 1; msk &= msk - 1u;
            float4 c  = sck[k];
            float4 a2 = sax[k];
            float e0 = ce0 - c.x, e1 = ce1 - c.y, e2 = ce2 - c.z;
            float dd = fmaf(e0, e0, fmaf(e1, e1, e2 * e2));
            float arg = fminf(fmaxf(dd * a2.x, 1e-7f), 100.f);
            float omp;
            if (arg < 0.0625f) omp = arg * (1.f + arg * (-0.5f + arg * (1.f / 6.f)));
            else               omp = 1.f - __expf(-arg);
            m -= __logf(omp);    // -log1p(-p)
        }
    }

    // block reduction of 3 scalars
    #pragma unroll
    for (int o = 16; o; o >>= 1) {
        m    += __shfl_down_sync(0xFFFFFFFFu, m, o);
        ss   += __shfl_down_sync(0xFFFFFFFFu, ss, o);
        aloc += __shfl_down_sync(0xFFFFFFFFu, aloc, o);
    }
    if (lane == 0) { rm[wid] = m; rs[wid] = ss; ra[wid] = aloc; }
    __syncthreads();
    if (tid == 0) {
        float tm = 0.f, ts = 0.f, ta = 0.f;
        #pragma unroll
        for (int i = 0; i < 8; i++) { tm += rm[i]; ts += rs[i]; ta += ra[i]; }
        atomicAdd(&g_accum[A_MSUM], tm);
        atomicAdd(&g_accum[A_SSUM], ts);
        atomicAdd(&g_accum[A_ACC],  ta);
        __threadfence();
        lastb = (atomicAdd(&g_ctr2, 1u) == (unsigned)(NBLK - 1));
    }
    __syncthreads();

    if (lastb) {   // finalize: inter-cluster hinge + combine + re-zero scratch
        float hs = 0.f;
        if (tid < B * K) {
            int bb = tid >> 5, kk = tid & 31;
            float4 ck = g_ck[tid];
            #pragma unroll
            for (int j = 0; j < K; j++) {
                if (j == kk) continue;
                float4 cj = g_ck[(bb << 5) | j];
                float f0 = ck.x - cj.x, f1 = ck.y - cj.y, f2 = ck.z - cj.z;
                float cd2 = fmaf(f0, f0, fmaf(f1, f1, f2 * f2));
                float d = sqrtf(cd2);
                float h = fmaxf(0.f, 1.f - d);
                hs += h * h;
            }
        }
        #pragma unroll
        for (int o = 16; o; o >>= 1) hs += __shfl_down_sync(0xFFFFFFFFu, hs, o);
        if (lane == 0) rm[wid] = hs;
        __syncthreads();
        if (tid == 0) {
            float htot = 0.f;
            #pragma unroll
            for (int i = 0; i < 8; i++) htot += rm[i];
            float msum = g_accum[A_MSUM];
            float ssum = g_accum[A_SSUM];
            float asum = g_accum[A_ACC];
            float loss = msum * (1.f / ((float)B * (float)NB * (float)K))
                       + ssum * (1.f / ((float)B * (float)K))
                       + htot * (1.f / (2.f * (float)K * (float)(K - 1) * (float)B));
            out[0] = loss;
            if (out_size > 1) out[1] = asum * (1.f / (float)NTOT);
        }
        __syncthreads();   // all reads of g_accum done before re-zero
        for (int i = tid; i < A_TOTAL; i += THREADS) g_accum[i] = 0.f;
        if (tid == 0) g_ctr2 = 0u;
    }
}

extern "C" void kernel_launch(void* const* d_in, const int* in_sizes, int n_in,
                              void* d_out, int out_size) {
    const float4* emb  = (const float4*)d_in[0];
    const float*  seed = (const float*)d_in[1];
    const float*  lab  = (const float*)d_in[2];
    float* out = (float*)d_out;

    k_pass1<<<NBLK, THREADS>>>(emb, lab);
    k_pass3<<<NBLK, THREADS>>>(emb, seed, lab, out, out_size);
}

// round 7
// speedup vs baseline: 1.4143x; 1.0082x over previous
#include <cuda_runtime.h>
#include <cuda_bf16.h>

#define B     4
#define NB    131072
#define K     32
#define NTOT  (B*NB)
#define HALFS 384.0f
#define INVHALF (1.0f/384.0f)

#define THREADS 256
#define GP      2
#define PPB     (THREADS*GP)        // 512 points per block
#define NBLK    (NTOT/PPB)          // 1024 blocks
#define BPB_SHIFT 8                 // 256 blocks per batch

// ---- persistent device scratch (no allocations allowed) ----
#define A_SUM   0      // 512 floats: [(b*K+k)*4 + c]  c=0..2 ce sums, c=3 sigma sum
#define A_CNT   512    // 128 counts
#define A_MSUM  640    // mask-loss scalar
#define A_SSUM  641    // smooth+seed (w-weighted) scalar
#define A_ACC   642    // accuracy count
#define A_TOTAL 643

__device__ float    g_accum[A_TOTAL];   // zero-init at load; re-zeroed by pass3 finalize
__device__ float4   g_ck [B*K];         // cx, cy, cz, thr(=87*2sig^2)
__device__ float4   g_aux[B*K];         // 1/(2sig^2), sigma, 1/cnt, 0
__device__ unsigned g_ctr1, g_ctr2;

// ---------------- pass 1: per-(batch,cluster) sums + finalize centers ----------------
__global__ void __launch_bounds__(THREADS, 6) k_pass1(const float4* __restrict__ emb,
                                                      const float*  __restrict__ lab) {
    __shared__ float4 stg4[THREADS];
    __shared__ int    stgi[THREADS];
    __shared__ float  sbin[K * 5];
    __shared__ bool   lastb;

    int tid  = threadIdx.x;
    int lane = tid & 31;
    int wb   = tid & ~31;
    int b    = blockIdx.x >> BPB_SHIFT;

    if (tid < K * 5) sbin[tid] = 0.f;
    __syncthreads();

    float a0 = 0.f, a1 = 0.f, a2 = 0.f, a3 = 0.f, ac = 0.f;
    int base = blockIdx.x * PPB + tid;

    #pragma unroll 1
    for (int g = 0; g < GP; g++) {
        int n = base + g * THREADS;
        float4 e = emb[n];
        const float* L = lab + (size_t)n * 6;
        float c0 = e.x + (L[1] - HALFS) * INVHALF;
        float c1 = e.y + (L[2] - HALFS) * INVHALF;
        float c2 = e.z + (L[3] - HALFS) * INVHALF;
        int inst = (int)L[5];
        inst = max(0, min(K - 1, inst));

        stg4[tid] = make_float4(c0, c1, c2, e.w);
        stgi[tid] = inst;
        __syncwarp();
        // lane k owns cluster k: scan this warp's 32 staged points
        #pragma unroll
        for (int i = 0; i < 32; i++) {
            float4 v = stg4[wb + i];   // broadcast LDS.128
            int   ii = stgi[wb + i];   // broadcast LDS.32
            if (ii == lane) { a0 += v.x; a1 += v.y; a2 += v.z; a3 += v.w; ac += 1.f; }
        }
        __syncwarp();
    }

    // per-warp partials -> block bins (lane-distinct addresses, tiny)
    atomicAdd(&sbin[lane * 5 + 0], a0);
    atomicAdd(&sbin[lane * 5 + 1], a1);
    atomicAdd(&sbin[lane * 5 + 2], a2);
    atomicAdd(&sbin[lane * 5 + 3], a3);
    atomicAdd(&sbin[lane * 5 + 4], ac);
    __syncthreads();

    // block bins -> global
    if (tid < K * 5) {
        int k = tid / 5, c = tid - k * 5;
        float v = sbin[tid];
        if (c < 4) atomicAdd(&g_accum[A_SUM + ((b << 5) + k) * 4 + c], v);
        else       atomicAdd(&g_accum[A_CNT + (b << 5) + k], v);
    }
    __threadfence();
    __syncthreads();
    if (tid == 0) lastb = (atomicAdd(&g_ctr1, 1u) == (unsigned)(NBLK - 1));
    __syncthreads();

    if (lastb) {   // finalize: centers / sigmas / weights
        if (tid < B * K) {
            float cnt = fmaxf(g_accum[A_CNT + tid], 1.f);
            float inv = 1.f / cnt;
            float cx = g_accum[A_SUM + tid * 4 + 0] * inv;
            float cy = g_accum[A_SUM + tid * 4 + 1] * inv;
            float cz = g_accum[A_SUM + tid * 4 + 2] * inv;
            float sg = g_accum[A_SUM + tid * 4 + 3] * inv;
            float s2 = 2.f * sg * sg;
            g_ck [tid] = make_float4(cx, cy, cz, 87.f * s2);
            g_aux[tid] = make_float4(1.f / s2, sg, inv, 0.f);
        }
        if (tid == 0) g_ctr1 = 0u;
    }
}

// own-cluster + rare-log epilogue for one point; returns via accumulators
__device__ __forceinline__ void point_epilogue(
    const float4* sck, const float4* sax,
    float ce0, float ce1, float ce2, float ew, float seed,
    int inst, int bi, unsigned msk,
    float& m, float& ss, float& aloc)
{
    float4 ci = sck[inst];
    float4 ax = sax[inst];
    float d0 = ce0 - ci.x, d1 = ce1 - ci.y, d2 = ce2 - ci.z;
    float di = fmaf(d0, d0, fmaf(d1, d1, d2 * d2));
    float argi = fminf(fmaxf(di * ax.x, 1e-7f), 100.f);
    m += argi;
    float pi = __expf(-argi);
    float ds = seed - pi;
    ss += ax.z * (fabsf(ew - ax.y) + ds * ds);   // w * (smooth + seed terms)
    aloc += (bi == inst) ? 1.f : 0.f;

    msk &= ~(1u << inst);
    while (msk) {
        int k = __ffs(msk) - 1; msk &= msk - 1u;
        float4 c  = sck[k];
        float4 a2 = sax[k];
        float e0 = ce0 - c.x, e1 = ce1 - c.y, e2 = ce2 - c.z;
        float dd = fmaf(e0, e0, fmaf(e1, e1, e2 * e2));
        float arg = fminf(fmaxf(dd * a2.x, 1e-7f), 100.f);
        float omp;
        if (arg < 0.0625f) omp = arg * (1.f + arg * (-0.5f + arg * (1.f / 6.f)));
        else               omp = 1.f - __expf(-arg);
        m -= __logf(omp);    // -log1p(-p)
    }
}

// ---------------- pass 3: main N x K loop (2-point ILP) + finalize ----------------
__global__ void __launch_bounds__(THREADS, 4) k_pass3(const float4* __restrict__ emb,
                                                      const float*  __restrict__ seedp,
                                                      const float*  __restrict__ lab,
                                                      float* __restrict__ out, int out_size) {
    __shared__ float4 sck[K];     // cx,cy,cz,thr
    __shared__ float4 sax[K];     // inv2s2, sigma, 1/cnt, 0
    __shared__ float  rm[8], rs[8], ra[8];
    __shared__ bool   lastb;

    int tid  = threadIdx.x;
    int lane = tid & 31;
    int wid  = tid >> 5;
    int b    = blockIdx.x >> BPB_SHIFT;

    if (tid < K) { sck[tid] = g_ck[(b << 5) + tid]; sax[tid] = g_aux[(b << 5) + tid]; }
    __syncthreads();

    // two points per thread, processed concurrently for ILP
    int nA = blockIdx.x * PPB + tid;
    int nB = nA + THREADS;

    float4 eA = emb[nA];
    float4 eB = emb[nB];
    const float* LA = lab + (size_t)nA * 6;
    const float* LB = lab + (size_t)nB * 6;
    float seedA = seedp[nA];
    float seedB = seedp[nB];

    float ceA0 = eA.x + (LA[1] - HALFS) * INVHALF;
    float ceA1 = eA.y + (LA[2] - HALFS) * INVHALF;
    float ceA2 = eA.z + (LA[3] - HALFS) * INVHALF;
    float ceB0 = eB.x + (LB[1] - HALFS) * INVHALF;
    float ceB1 = eB.y + (LB[2] - HALFS) * INVHALF;
    float ceB2 = eB.z + (LB[3] - HALFS) * INVHALF;
    int instA = (int)LA[5]; instA = max(0, min(K - 1, instA));
    int instB = (int)LB[5]; instB = max(0, min(K - 1, instB));

    float    bestA = 3.4e38f, bestB = 3.4e38f;
    int      biA = 0, biB = 0;
    unsigned mskA = 0u, mskB = 0u;

    #pragma unroll 4
    for (int k = 0; k < K; k++) {
        float4 c = sck[k];
        float a0 = ceA0 - c.x, a1 = ceA1 - c.y, a2 = ceA2 - c.z;
        float b0 = ceB0 - c.x, b1 = ceB1 - c.y, b2 = ceB2 - c.z;
        float dA = fmaf(a0, a0, fmaf(a1, a1, a2 * a2));
        float dB = fmaf(b0, b0, fmaf(b1, b1, b2 * b2));
        bool fA = dA < bestA;
        bool fB = dB < bestB;
        bestA = fA ? dA : bestA;  biA = fA ? k : biA;
        bestB = fB ? dB : bestB;  biB = fB ? k : biB;
        mskA |= (dA < c.w) ? (1u << k) : 0u;
        mskB |= (dB < c.w) ? (1u << k) : 0u;
    }

    float m = 0.f, ss = 0.f, aloc = 0.f;
    point_epilogue(sck, sax, ceA0, ceA1, ceA2, eA.w, seedA, instA, biA, mskA, m, ss, aloc);
    point_epilogue(sck, sax, ceB0, ceB1, ceB2, eB.w, seedB, instB, biB, mskB, m, ss, aloc);

    // block reduction of 3 scalars
    #pragma unroll
    for (int o = 16; o; o >>= 1) {
        m    += __shfl_down_sync(0xFFFFFFFFu, m, o);
        ss   += __shfl_down_sync(0xFFFFFFFFu, ss, o);
        aloc += __shfl_down_sync(0xFFFFFFFFu, aloc, o);
    }
    if (lane == 0) { rm[wid] = m; rs[wid] = ss; ra[wid] = aloc; }
    __syncthreads();
    if (tid == 0) {
        float tm = 0.f, ts = 0.f, ta = 0.f;
        #pragma unroll
        for (int i = 0; i < 8; i++) { tm += rm[i]; ts += rs[i]; ta += ra[i]; }
        atomicAdd(&g_accum[A_MSUM], tm);
        atomicAdd(&g_accum[A_SSUM], ts);
        atomicAdd(&g_accum[A_ACC],  ta);
        __threadfence();
        lastb = (atomicAdd(&g_ctr2, 1u) == (unsigned)(NBLK - 1));
    }
    __syncthreads();

    if (lastb) {   // finalize: inter-cluster hinge + combine + re-zero scratch
        float hs = 0.f;
        if (tid < B * K) {
            int bb = tid >> 5, kk = tid & 31;
            float4 ck = g_ck[tid];
            #pragma unroll
            for (int j = 0; j < K; j++) {
                if (j == kk) continue;
                float4 cj = g_ck[(bb << 5) | j];
                float f0 = ck.x - cj.x, f1 = ck.y - cj.y, f2 = ck.z - cj.z;
                float cd2 = fmaf(f0, f0, fmaf(f1, f1, f2 * f2));
                float d = sqrtf(cd2);
                float h = fmaxf(0.f, 1.f - d);
                hs += h * h;
            }
        }
        #pragma unroll
        for (int o = 16; o; o >>= 1) hs += __shfl_down_sync(0xFFFFFFFFu, hs, o);
        if (lane == 0) rm[wid] = hs;
        __syncthreads();
        if (tid == 0) {
            float htot = 0.f;
            #pragma unroll
            for (int i = 0; i < 8; i++) htot += rm[i];
            float msum = g_accum[A_MSUM];
            float ssum = g_accum[A_SSUM];
            float asum = g_accum[A_ACC];
            float loss = msum * (1.f / ((float)B * (float)NB * (float)K))
                       + ssum * (1.f / ((float)B * (float)K))
                       + htot * (1.f / (2.f * (float)K * (float)(K - 1) * (float)B));
            out[0] = loss;
            if (out_size > 1) out[1] = asum * (1.f / (float)NTOT);
        }
        __syncthreads();   // all reads of g_accum done before re-zero
        for (int i = tid; i < A_TOTAL; i += THREADS) g_accum[i] = 0.f;
        if (tid == 0) g_ctr2 = 0u;
    }
}

extern "C" void kernel_launch(void* const* d_in, const int* in_sizes, int n_in,
                              void* d_out, int out_size) {
    const float4* emb  = (const float4*)d_in[0];
    const float*  seed = (const float*)d_in[1];
    const float*  lab  = (const float*)d_in[2];
    float* out = (float*)d_out;

    k_pass1<<<NBLK, THREADS>>>(emb, lab);
    k_pass3<<<NBLK, THREADS>>>(emb, seed, lab, out, out_size);
}